// round 9
// baseline (speedup 1.0000x reference)
#include <cuda_runtime.h>
#include <cuda_fp16.h>
#include <cstdint>

namespace {
constexpr int S_    = 2048;
constexpr int H_    = 32;
constexpr int G_    = 4;
constexpr int D_    = 128;
constexpr int QSTR  = 4096;   // H*D floats per token (q, out)
constexpr int KSTR  = 1024;   // HKV*D per token (k, v)
constexpr int BM    = 128;    // q rows per CTA (64 per team)
constexpr int BN    = 64;     // kv rows per tile
constexpr int NT    = 256;    // threads (2 teams x 128)
constexpr int STRIDE = 136;   // smem row stride in halves (128 + 8 pad)
constexpr int KV_ELE = BN * STRIDE;               // halves per buffer
// smem: Q (128 rows) + per-team double-buffered K and V (2 teams x 2 bufs each)
constexpr int SMEM_BYTES = (BM * STRIDE + 8 * KV_ELE) * 2;
}

// fp16 copies of K/V (scratch)
__device__ __align__(16) half g_kh[2 * S_ * KSTR];
__device__ __align__(16) half g_vh[2 * S_ * KSTR];

__device__ __forceinline__ uint32_t smem_u32(const void* p) {
    return (uint32_t)__cvta_generic_to_shared(p);
}
__device__ __forceinline__ void cp_async16(uint32_t dst, const void* src) {
    asm volatile("cp.async.cg.shared.global [%0], [%1], 16;\n" :: "r"(dst), "l"(src));
}
__device__ __forceinline__ void ldm_x4(uint32_t& r0, uint32_t& r1, uint32_t& r2, uint32_t& r3, uint32_t a) {
    asm volatile("ldmatrix.sync.aligned.m8n8.x4.shared.b16 {%0,%1,%2,%3}, [%4];\n"
        : "=r"(r0), "=r"(r1), "=r"(r2), "=r"(r3) : "r"(a));
}
__device__ __forceinline__ void ldm_x4_t(uint32_t& r0, uint32_t& r1, uint32_t& r2, uint32_t& r3, uint32_t a) {
    asm volatile("ldmatrix.sync.aligned.m8n8.x4.trans.shared.b16 {%0,%1,%2,%3}, [%4];\n"
        : "=r"(r0), "=r"(r1), "=r"(r2), "=r"(r3) : "r"(a));
}
__device__ __forceinline__ void mma16816(float* c, const uint32_t* a, uint32_t b0, uint32_t b1) {
    asm volatile("mma.sync.aligned.m16n8k16.row.col.f32.f16.f16.f32 "
        "{%0,%1,%2,%3}, {%4,%5,%6,%7}, {%8,%9}, {%0,%1,%2,%3};\n"
        : "+f"(c[0]), "+f"(c[1]), "+f"(c[2]), "+f"(c[3])
        : "r"(a[0]), "r"(a[1]), "r"(a[2]), "r"(a[3]), "r"(b0), "r"(b1));
}
__device__ __forceinline__ uint32_t packh2(float x, float y) {
    half2 h = __floats2half2_rn(x, y);
    return *reinterpret_cast<uint32_t*>(&h);
}
// p_half2 = ex2.approx.f16x2( half2(lo, hi) )
__device__ __forceinline__ uint32_t exp2_h2(float lo, float hi) {
    uint32_t h, p;
    asm volatile("cvt.rn.f16x2.f32 %0, %1, %2;\n" : "=r"(h) : "f"(hi), "f"(lo));
    asm volatile("ex2.approx.f16x2 %0, %1;\n" : "=r"(p) : "r"(h));
    return p;
}
__device__ __forceinline__ void team_bar(int team) {
    asm volatile("bar.sync %0, 128;\n" :: "r"(team + 1) : "memory");
}

// ---- K/V fp32 -> fp16 convert pass ----
__global__ void cvt_kernel(const float* __restrict__ k, const float* __restrict__ v) {
    const size_t n4 = (size_t)2 * S_ * KSTR / 4;
    for (size_t i = (size_t)blockIdx.x * blockDim.x + threadIdx.x;
         i < 2 * n4; i += (size_t)gridDim.x * blockDim.x) {
        bool isK = i < n4;
        size_t ii = isK ? i : i - n4;
        float4 f = isK ? ((const float4*)k)[ii] : ((const float4*)v)[ii];
        uint2 h;
        h.x = packh2(f.x, f.y);
        h.y = packh2(f.z, f.w);
        ((uint2*)(isK ? g_kh : g_vh))[ii] = h;
    }
}

__global__ __launch_bounds__(NT, 1)
void fa2_kernel(const float* __restrict__ q, float* __restrict__ o)
{
    extern __shared__ __align__(16) half smem[];
    half* sQ    = smem;                       // BM * STRIDE
    half* sKbuf = smem + BM * STRIDE;         // 4 bufs: team*2 + (j&1)
    half* sVbuf = sKbuf + 4 * KV_ELE;         // 4 bufs

    const int tid  = threadIdx.x;
    const int lane = tid & 31;
    const int team = tid >> 7;                // 0: q rows 0-63, 1: rows 64-127
    const int ttid = tid & 127;               // thread within team
    const int wi   = (tid >> 5) & 3;          // warp within team
    const int qt   = (int)gridDim.x - 1 - (int)blockIdx.x;  // heavy tiles first
    const int hq   = blockIdx.y;
    const int b    = blockIdx.z;
    const int hkv  = hq / G_;
    const int qbase = qt * BM;
    // team A covers rows [0,64) -> tiles up to (qbase+64)/BN; team B all of them
    const int ntile = (qbase + (team + 1) * 64) / BN;   // 2qt+1 or 2qt+2

    const size_t tok0 = (size_t)b * S_ + qbase;
    const half* kg = g_kh + ((size_t)b * S_) * KSTR + (size_t)hkv * D_;
    const half* vg = g_vh + ((size_t)b * S_) * KSTR + (size_t)hkv * D_;

    // per-team KV loader (128 threads of this team only)
    auto load_kv = [&](int j) {
        const half* kt = kg + (size_t)(j * BN) * KSTR;
        const half* vt = vg + (size_t)(j * BN) * KSTR;
        half* dK = sKbuf + (team * 2 + (j & 1)) * KV_ELE;
        half* dV = sVbuf + (team * 2 + (j & 1)) * KV_ELE;
        #pragma unroll
        for (int i = ttid; i < BN * 16; i += 128) {
            int r = i >> 4, c = (i & 15) * 8;
            cp_async16(smem_u32(dK + r * STRIDE + c), kt + (size_t)r * KSTR + c);
            cp_async16(smem_u32(dV + r * STRIDE + c), vt + (size_t)r * KSTR + c);
        }
    };
    load_kv(0);
    asm volatile("cp.async.commit_group;\n");
    if (1 < ntile) load_kv(1);
    asm volatile("cp.async.commit_group;\n");

    // ---- stage Q (fp32 -> fp16), all 256 threads, one full sync ----
    const float* qg = q + tok0 * QSTR + (size_t)hq * D_;
    for (int i = tid; i < BM * 32; i += NT) {
        int r = i >> 5, c = (i & 31) * 4;
        float4 f = *(const float4*)(qg + (size_t)r * QSTR + c);
        half2* d = (half2*)(sQ + r * STRIDE + c);
        d[0] = __floats2half2_rn(f.x, f.y);
        d[1] = __floats2half2_rn(f.z, f.w);
    }
    __syncthreads();

    // ---- Q fragments (persistent); warp owns rows team*64 + wi*16 .. +15 ----
    const int qrow0 = team * 64 + wi * 16;
    uint32_t qf[8][4];
    {
        int j = lane >> 3, m = lane & 7;
        int row = qrow0 + ((j & 1) ? 8 : 0) + m;
        int col = (j >= 2) ? 8 : 0;
        #pragma unroll
        for (int kc = 0; kc < 8; kc++) {
            uint32_t a = smem_u32(sQ + row * STRIDE + kc * 16 + col);
            ldm_x4(qf[kc][0], qf[kc][1], qf[kc][2], qf[kc][3], a);
        }
    }

    constexpr float SL = 0.08838834764831845f * 1.4426950408889634f;  // SCALE*log2(e)
    float ot[16][4];
    #pragma unroll
    for (int t = 0; t < 16; t++)
        #pragma unroll
        for (int i = 0; i < 4; i++) ot[t][i] = 0.f;
    float lacc[4] = {0.f, 0.f, 0.f, 0.f};  // l via ones-column mma
    float m0 = -1e30f, m1 = -1e30f;

    const uint32_t onesB = (lane < 4) ? 0x3C003C00u : 0u;

    const int r0g = qbase + qrow0 + (lane >> 2);
    const int r1g = r0g + 8;
    const int wrow = qbase + qrow0;

    for (int j = 0; j < ntile; j++) {
        asm volatile("cp.async.wait_group 1;\n");
        team_bar(team);

        const half* sK = sKbuf + (team * 2 + (j & 1)) * KV_ELE;
        const half* sV = sVbuf + (team * 2 + (j & 1)) * KV_ELE;

        bool skip = (wrow + 15) < j * BN;
        if (!skip) {
            // ---- S = Q K^T (raw scores) ----
            float sc[8][4];
            #pragma unroll
            for (int t = 0; t < 8; t++)
                #pragma unroll
                for (int i = 0; i < 4; i++) sc[t][i] = 0.f;
            {
                int jj = lane >> 3, mm = lane & 7;
                int rn = ((jj >= 2) ? 8 : 0) + mm;
                int ck = (jj & 1) ? 8 : 0;
                #pragma unroll
                for (int kc = 0; kc < 8; kc++) {
                    #pragma unroll
                    for (int np = 0; np < 4; np++) {
                        uint32_t a = smem_u32(sK + (np * 16 + rn) * STRIDE + kc * 16 + ck);
                        uint32_t b0, b1, b2, b3;
                        ldm_x4(b0, b1, b2, b3, a);
                        mma16816(sc[2 * np],     qf[kc], b0, b1);
                        mma16816(sc[2 * np + 1], qf[kc], b2, b3);
                    }
                }
            }

            // ---- causal mask on raw scores (straddle tiles only) ----
            bool needMask = (j * BN + BN - 1) > wrow;
            if (needMask) {
                int c0 = j * BN + (lane & 3) * 2;
                #pragma unroll
                for (int nt = 0; nt < 8; nt++) {
                    int cc = c0 + nt * 8;
                    if (cc     > r0g) sc[nt][0] = -1e30f;
                    if (cc + 1 > r0g) sc[nt][1] = -1e30f;
                    if (cc     > r1g) sc[nt][2] = -1e30f;
                    if (cc + 1 > r1g) sc[nt][3] = -1e30f;
                }
            }

            // ---- max on RAW scores (max commutes with positive scale) ----
            float t0 = sc[0][0], t1 = sc[0][2];
            #pragma unroll
            for (int nt = 0; nt < 8; nt++) {
                t0 = fmaxf(t0, fmaxf(sc[nt][0], sc[nt][1]));
                t1 = fmaxf(t1, fmaxf(sc[nt][2], sc[nt][3]));
            }
            t0 = fmaxf(t0, __shfl_xor_sync(0xffffffffu, t0, 1));
            t0 = fmaxf(t0, __shfl_xor_sync(0xffffffffu, t0, 2));
            t1 = fmaxf(t1, __shfl_xor_sync(0xffffffffu, t1, 1));
            t1 = fmaxf(t1, __shfl_xor_sync(0xffffffffu, t1, 2));
            float nm0 = fmaxf(m0, t0 * SL);
            float nm1 = fmaxf(m1, t1 * SL);
            float a0 = exp2f(m0 - nm0), a1 = exp2f(m1 - nm1);
            m0 = nm0; m1 = nm1;

            // ---- h = s*SL - m ----
            #pragma unroll
            for (int nt = 0; nt < 8; nt++) {
                sc[nt][0] = fmaf(sc[nt][0], SL, -m0);
                sc[nt][1] = fmaf(sc[nt][1], SL, -m0);
                sc[nt][2] = fmaf(sc[nt][2], SL, -m1);
                sc[nt][3] = fmaf(sc[nt][3], SL, -m1);
            }

            // ---- rescale O and l ----
            #pragma unroll
            for (int t = 0; t < 16; t++) {
                ot[t][0] *= a0; ot[t][1] *= a0;
                ot[t][2] *= a1; ot[t][3] *= a1;
            }
            lacc[0] *= a0; lacc[2] *= a1;

            // ---- P = ex2(h) fp16x2; PV mma + l via ones-column mma ----
            {
                int jj = lane >> 3, mm = lane & 7;
                int rk = (jj & 1) * 8 + mm;
                int cn = (jj >= 2) ? 8 : 0;
                #pragma unroll
                for (int kvc = 0; kvc < 4; kvc++) {
                    uint32_t af[4];
                    af[0] = exp2_h2(sc[2 * kvc][0],     sc[2 * kvc][1]);
                    af[1] = exp2_h2(sc[2 * kvc][2],     sc[2 * kvc][3]);
                    af[2] = exp2_h2(sc[2 * kvc + 1][0], sc[2 * kvc + 1][1]);
                    af[3] = exp2_h2(sc[2 * kvc + 1][2], sc[2 * kvc + 1][3]);
                    mma16816(lacc, af, onesB, onesB);
                    #pragma unroll
                    for (int dp = 0; dp < 8; dp++) {
                        uint32_t b0, b1, b2, b3;
                        uint32_t a = smem_u32(sV + (kvc * 16 + rk) * STRIDE + dp * 16 + cn);
                        ldm_x4_t(b0, b1, b2, b3, a);
                        mma16816(ot[2 * dp],     af, b0, b1);
                        mma16816(ot[2 * dp + 1], af, b2, b3);
                    }
                }
            }
        }

        team_bar(team);                     // team done with buf (j&1)
        if (j + 2 < ntile) load_kv(j + 2);
        asm volatile("cp.async.commit_group;\n");
    }

    // ---- epilogue: broadcast l (col 0 lives in lane&~3), normalize, store ----
    float lr0 = __shfl_sync(0xffffffffu, lacc[0], lane & ~3);
    float lr1 = __shfl_sync(0xffffffffu, lacc[2], lane & ~3);
    float inv0 = 1.f / lr0, inv1 = 1.f / lr1;
    float* og = o + tok0 * QSTR + (size_t)hq * D_;
    int rr0 = qrow0 + (lane >> 2);
    #pragma unroll
    for (int nt = 0; nt < 16; nt++) {
        int c = nt * 8 + (lane & 3) * 2;
        float2 w0 = make_float2(ot[nt][0] * inv0, ot[nt][1] * inv0);
        float2 w1 = make_float2(ot[nt][2] * inv1, ot[nt][3] * inv1);
        *(float2*)(og + (size_t)rr0 * QSTR + c)       = w0;
        *(float2*)(og + (size_t)(rr0 + 8) * QSTR + c) = w1;
    }
}

extern "C" void kernel_launch(void* const* d_in, const int* in_sizes, int n_in,
                              void* d_out, int out_size)
{
    const float* q = (const float*)d_in[0];
    const float* k = (const float*)d_in[1];
    const float* v = (const float*)d_in[2];
    float* o = (float*)d_out;

    cvt_kernel<<<2048, 256>>>(k, v);

    cudaFuncSetAttribute(fa2_kernel, cudaFuncAttributeMaxDynamicSharedMemorySize, SMEM_BYTES);
    dim3 grid(S_ / BM, H_, 2);
    fa2_kernel<<<grid, NT, SMEM_BYTES>>>(q, o);
}

// round 10
// speedup vs baseline: 1.6703x; 1.6703x over previous
#include <cuda_runtime.h>
#include <cuda_fp16.h>
#include <cstdint>

namespace {
constexpr int S_    = 2048;
constexpr int H_    = 32;
constexpr int G_    = 4;
constexpr int D_    = 128;
constexpr int QSTR  = 4096;   // H*D floats per token (q, out)
constexpr int KSTR  = 1024;   // HKV*D per token (k, v)
constexpr int BM    = 64;     // q rows per CTA
constexpr int BN    = 64;     // kv rows per tile
constexpr int NT    = 128;    // threads (4 warps)
constexpr int STRIDE = 136;   // smem row stride in halves (128 + 8 pad)
constexpr int KV_ELE = BN * STRIDE;
// sQ (64 rows) + 2*sK + 2*sV
constexpr int SMEM_BYTES = (BM * STRIDE + 4 * KV_ELE) * 2;   // 87,040 B
}

// fp16 copies of K/V (scratch)
__device__ __align__(16) half g_kh[2 * S_ * KSTR];
__device__ __align__(16) half g_vh[2 * S_ * KSTR];

__device__ __forceinline__ uint32_t smem_u32(const void* p) {
    return (uint32_t)__cvta_generic_to_shared(p);
}
__device__ __forceinline__ void cp_async16(uint32_t dst, const void* src) {
    asm volatile("cp.async.cg.shared.global [%0], [%1], 16;\n" :: "r"(dst), "l"(src));
}
__device__ __forceinline__ void ldm_x4(uint32_t& r0, uint32_t& r1, uint32_t& r2, uint32_t& r3, uint32_t a) {
    asm volatile("ldmatrix.sync.aligned.m8n8.x4.shared.b16 {%0,%1,%2,%3}, [%4];\n"
        : "=r"(r0), "=r"(r1), "=r"(r2), "=r"(r3) : "r"(a));
}
__device__ __forceinline__ void ldm_x4_t(uint32_t& r0, uint32_t& r1, uint32_t& r2, uint32_t& r3, uint32_t a) {
    asm volatile("ldmatrix.sync.aligned.m8n8.x4.trans.shared.b16 {%0,%1,%2,%3}, [%4];\n"
        : "=r"(r0), "=r"(r1), "=r"(r2), "=r"(r3) : "r"(a));
}
__device__ __forceinline__ void mma16816(float* c, const uint32_t* a, uint32_t b0, uint32_t b1) {
    asm volatile("mma.sync.aligned.m16n8k16.row.col.f32.f16.f16.f32 "
        "{%0,%1,%2,%3}, {%4,%5,%6,%7}, {%8,%9}, {%0,%1,%2,%3};\n"
        : "+f"(c[0]), "+f"(c[1]), "+f"(c[2]), "+f"(c[3])
        : "r"(a[0]), "r"(a[1]), "r"(a[2]), "r"(a[3]), "r"(b0), "r"(b1));
}
__device__ __forceinline__ uint32_t packh2(float x, float y) {
    half2 h = __floats2half2_rn(x, y);
    return *reinterpret_cast<uint32_t*>(&h);
}
// p_half2 = ex2.approx.f16x2( half2(lo, hi) )
__device__ __forceinline__ uint32_t exp2_h2(float lo, float hi) {
    uint32_t h, p;
    asm volatile("cvt.rn.f16x2.f32 %0, %1, %2;\n" : "=r"(h) : "f"(hi), "f"(lo));
    asm volatile("ex2.approx.f16x2 %0, %1;\n" : "=r"(p) : "r"(h));
    return p;
}

// ---- K/V fp32 -> fp16 convert pass ----
__global__ void cvt_kernel(const float* __restrict__ k, const float* __restrict__ v) {
    const size_t n4 = (size_t)2 * S_ * KSTR / 4;
    for (size_t i = (size_t)blockIdx.x * blockDim.x + threadIdx.x;
         i < 2 * n4; i += (size_t)gridDim.x * blockDim.x) {
        bool isK = i < n4;
        size_t ii = isK ? i : i - n4;
        float4 f = isK ? ((const float4*)k)[ii] : ((const float4*)v)[ii];
        uint2 h;
        h.x = packh2(f.x, f.y);
        h.y = packh2(f.z, f.w);
        ((uint2*)(isK ? g_kh : g_vh))[ii] = h;
    }
}

__global__ __launch_bounds__(NT, 2)
void fa2_kernel(const float* __restrict__ q, float* __restrict__ o)
{
    extern __shared__ __align__(16) half smem[];
    half* sQ    = smem;                     // BM * STRIDE
    half* sKbuf = smem + BM * STRIDE;       // 2 bufs
    half* sVbuf = sKbuf + 2 * KV_ELE;       // 2 bufs

    const int tid  = threadIdx.x;
    const int warp = tid >> 5;
    const int lane = tid & 31;
    const int qt   = (int)gridDim.x - 1 - (int)blockIdx.x;  // heavy tiles first
    const int hq   = blockIdx.y;
    const int b    = blockIdx.z;
    const int hkv  = hq / G_;
    const int qbase = qt * BM;
    const int ntile = (qbase + BM) / BN;   // = qt + 1 >= 1

    const size_t tok0 = (size_t)b * S_ + qbase;
    const half* kg = g_kh + ((size_t)b * S_) * KSTR + (size_t)hkv * D_;
    const half* vg = g_vh + ((size_t)b * S_) * KSTR + (size_t)hkv * D_;

    auto load_kv = [&](int j, int buf) {
        const half* kt = kg + (size_t)(j * BN) * KSTR;
        const half* vt = vg + (size_t)(j * BN) * KSTR;
        half* dK = sKbuf + buf * KV_ELE;
        half* dV = sVbuf + buf * KV_ELE;
        #pragma unroll
        for (int i = tid; i < BN * 16; i += NT) {
            int r = i >> 4, c = (i & 15) * 8;
            cp_async16(smem_u32(dK + r * STRIDE + c), kt + (size_t)r * KSTR + c);
            cp_async16(smem_u32(dV + r * STRIDE + c), vt + (size_t)r * KSTR + c);
        }
    };
    load_kv(0, 0);
    asm volatile("cp.async.commit_group;\n");
    if (1 < ntile) load_kv(1, 1);
    asm volatile("cp.async.commit_group;\n");

    // ---- stage Q (fp32 -> fp16) while cp.async is in flight ----
    const float* qg = q + tok0 * QSTR + (size_t)hq * D_;
    for (int i = tid; i < BM * 32; i += NT) {
        int r = i >> 5, c = (i & 31) * 4;
        float4 f = *(const float4*)(qg + (size_t)r * QSTR + c);
        half2* d = (half2*)(sQ + r * STRIDE + c);
        d[0] = __floats2half2_rn(f.x, f.y);
        d[1] = __floats2half2_rn(f.z, f.w);
    }
    __syncthreads();

    // ---- Q fragments (persistent); warp owns rows warp*16 .. +15 ----
    uint32_t qf[8][4];
    {
        int j = lane >> 3, m = lane & 7;
        int row = warp * 16 + ((j & 1) ? 8 : 0) + m;
        int col = (j >= 2) ? 8 : 0;
        #pragma unroll
        for (int kc = 0; kc < 8; kc++) {
            uint32_t a = smem_u32(sQ + row * STRIDE + kc * 16 + col);
            ldm_x4(qf[kc][0], qf[kc][1], qf[kc][2], qf[kc][3], a);
        }
    }

    constexpr float SL = 0.08838834764831845f * 1.4426950408889634f;  // SCALE*log2(e)
    float ot[16][4];
    #pragma unroll
    for (int t = 0; t < 16; t++)
        #pragma unroll
        for (int i = 0; i < 4; i++) ot[t][i] = 0.f;
    float lacc[4] = {0.f, 0.f, 0.f, 0.f};  // l via ones-column mma
    float m0 = -1e30f, m1 = -1e30f;

    const uint32_t onesB = (lane < 4) ? 0x3C003C00u : 0u;

    const int r0g = qbase + warp * 16 + (lane >> 2);
    const int r1g = r0g + 8;
    const int wrow = qbase + warp * 16;

    for (int j = 0; j < ntile; j++) {
        asm volatile("cp.async.wait_group 1;\n");
        __syncthreads();

        const half* sK = sKbuf + (j & 1) * KV_ELE;
        const half* sV = sVbuf + (j & 1) * KV_ELE;

        bool skip = (wrow + 15) < j * BN;
        if (!skip) {
            // ---- S = Q K^T (raw scores) ----
            float sc[8][4];
            #pragma unroll
            for (int t = 0; t < 8; t++)
                #pragma unroll
                for (int i = 0; i < 4; i++) sc[t][i] = 0.f;
            {
                int jj = lane >> 3, mm = lane & 7;
                int rn = ((jj >= 2) ? 8 : 0) + mm;
                int ck = (jj & 1) ? 8 : 0;
                #pragma unroll
                for (int kc = 0; kc < 8; kc++) {
                    #pragma unroll
                    for (int np = 0; np < 4; np++) {
                        uint32_t a = smem_u32(sK + (np * 16 + rn) * STRIDE + kc * 16 + ck);
                        uint32_t b0, b1, b2, b3;
                        ldm_x4(b0, b1, b2, b3, a);
                        mma16816(sc[2 * np],     qf[kc], b0, b1);
                        mma16816(sc[2 * np + 1], qf[kc], b2, b3);
                    }
                }
            }

            // ---- causal mask on raw scores (straddle tiles only) ----
            bool needMask = (j * BN + BN - 1) > wrow;
            if (needMask) {
                int c0 = j * BN + (lane & 3) * 2;
                #pragma unroll
                for (int nt = 0; nt < 8; nt++) {
                    int cc = c0 + nt * 8;
                    if (cc     > r0g) sc[nt][0] = -1e30f;
                    if (cc + 1 > r0g) sc[nt][1] = -1e30f;
                    if (cc     > r1g) sc[nt][2] = -1e30f;
                    if (cc + 1 > r1g) sc[nt][3] = -1e30f;
                }
            }

            // ---- max on RAW scores ----
            float t0 = sc[0][0], t1 = sc[0][2];
            #pragma unroll
            for (int nt = 0; nt < 8; nt++) {
                t0 = fmaxf(t0, fmaxf(sc[nt][0], sc[nt][1]));
                t1 = fmaxf(t1, fmaxf(sc[nt][2], sc[nt][3]));
            }
            t0 = fmaxf(t0, __shfl_xor_sync(0xffffffffu, t0, 1));
            t0 = fmaxf(t0, __shfl_xor_sync(0xffffffffu, t0, 2));
            t1 = fmaxf(t1, __shfl_xor_sync(0xffffffffu, t1, 1));
            t1 = fmaxf(t1, __shfl_xor_sync(0xffffffffu, t1, 2));
            float nm0 = fmaxf(m0, t0 * SL);
            float nm1 = fmaxf(m1, t1 * SL);
            float a0 = exp2f(m0 - nm0), a1 = exp2f(m1 - nm1);
            m0 = nm0; m1 = nm1;

            // ---- h = s*SL - m ----
            #pragma unroll
            for (int nt = 0; nt < 8; nt++) {
                sc[nt][0] = fmaf(sc[nt][0], SL, -m0);
                sc[nt][1] = fmaf(sc[nt][1], SL, -m0);
                sc[nt][2] = fmaf(sc[nt][2], SL, -m1);
                sc[nt][3] = fmaf(sc[nt][3], SL, -m1);
            }

            // ---- rescale O and l ----
            #pragma unroll
            for (int t = 0; t < 16; t++) {
                ot[t][0] *= a0; ot[t][1] *= a0;
                ot[t][2] *= a1; ot[t][3] *= a1;
            }
            lacc[0] *= a0; lacc[2] *= a1;

            // ---- P = ex2(h) fp16x2; PV mma + l via ones-column mma ----
            {
                int jj = lane >> 3, mm = lane & 7;
                int rk = (jj & 1) * 8 + mm;
                int cn = (jj >= 2) ? 8 : 0;
                #pragma unroll
                for (int kvc = 0; kvc < 4; kvc++) {
                    uint32_t af[4];
                    af[0] = exp2_h2(sc[2 * kvc][0],     sc[2 * kvc][1]);
                    af[1] = exp2_h2(sc[2 * kvc][2],     sc[2 * kvc][3]);
                    af[2] = exp2_h2(sc[2 * kvc + 1][0], sc[2 * kvc + 1][1]);
                    af[3] = exp2_h2(sc[2 * kvc + 1][2], sc[2 * kvc + 1][3]);
                    mma16816(lacc, af, onesB, onesB);
                    #pragma unroll
                    for (int dp = 0; dp < 8; dp++) {
                        uint32_t b0, b1, b2, b3;
                        uint32_t a = smem_u32(sV + (kvc * 16 + rk) * STRIDE + dp * 16 + cn);
                        ldm_x4_t(b0, b1, b2, b3, a);
                        mma16816(ot[2 * dp],     af, b0, b1);
                        mma16816(ot[2 * dp + 1], af, b2, b3);
                    }
                }
            }
        }

        __syncthreads();
        if (j + 2 < ntile) load_kv(j + 2, j & 1);
        asm volatile("cp.async.commit_group;\n");
    }

    // ---- epilogue: broadcast l (col 0 lives in lane&~3), normalize, store ----
    float lr0 = __shfl_sync(0xffffffffu, lacc[0], lane & ~3);
    float lr1 = __shfl_sync(0xffffffffu, lacc[2], lane & ~3);
    float inv0 = 1.f / lr0, inv1 = 1.f / lr1;
    float* og = o + tok0 * QSTR + (size_t)hq * D_;
    int rr0 = warp * 16 + (lane >> 2);
    #pragma unroll
    for (int nt = 0; nt < 16; nt++) {
        int c = nt * 8 + (lane & 3) * 2;
        float2 w0 = make_float2(ot[nt][0] * inv0, ot[nt][1] * inv0);
        float2 w1 = make_float2(ot[nt][2] * inv1, ot[nt][3] * inv1);
        *(float2*)(og + (size_t)rr0 * QSTR + c)       = w0;
        *(float2*)(og + (size_t)(rr0 + 8) * QSTR + c) = w1;
    }
}

extern "C" void kernel_launch(void* const* d_in, const int* in_sizes, int n_in,
                              void* d_out, int out_size)
{
    const float* q = (const float*)d_in[0];
    const float* k = (const float*)d_in[1];
    const float* v = (const float*)d_in[2];
    float* o = (float*)d_out;

    cvt_kernel<<<2048, 256>>>(k, v);

    cudaFuncSetAttribute(fa2_kernel, cudaFuncAttributeMaxDynamicSharedMemorySize, SMEM_BYTES);
    dim3 grid(S_ / BM, H_, 2);   // 32 x 32 x 2 = 2048 CTAs
    fa2_kernel<<<grid, NT, SMEM_BYTES>>>(q, o);
}